// round 1
// baseline (speedup 1.0000x reference)
#include <cuda_runtime.h>

// ---------------- scratch (static device globals; no allocation) ----------
#define MAXN 200704
__device__ __align__(16) float g_acc[MAXN * 4];   // sum of w * x[src] per dst
__device__ float g_cnt[MAXN];                     // in-degree per dst
__device__ int   g_is64;                          // edge_index dtype flag

// ---------------- fast math helpers --------------------------------------
__device__ __forceinline__ float fexp(float x) {
    float y;
    asm("ex2.approx.f32 %0, %1;" : "=f"(y) : "f"(x * 1.4426950408889634f));
    return y;
}
__device__ __forceinline__ float frcp(float x) {
    float y;
    asm("rcp.approx.f32 %0, %1;" : "=f"(y) : "f"(x));
    return y;
}
__device__ __forceinline__ float sigf(float x)  { return frcp(1.0f + fexp(-x)); }
__device__ __forceinline__ float tanhf_f(float x){ return 2.0f * sigf(2.0f * x) - 1.0f; }

// ---------------- kernel 1: zero scratch + detect index dtype ------------
__global__ void k_init(const void* __restrict__ ei, int E, int N) {
    int i = blockIdx.x * blockDim.x + threadIdx.x;
    int stride = gridDim.x * blockDim.x;
    for (int j = i; j < N * 4; j += stride) g_acc[j] = 0.0f;
    for (int j = i; j < N;     j += stride) g_cnt[j] = 0.0f;

    // dtype sniff: interpret as int64 and sample within the first E entries
    // (guaranteed in-bounds whether the buffer is 8E or 16E bytes).
    if (blockIdx.x == 0 && threadIdx.x < 32) {
        const long long* p = (const long long*)ei;
        long long step = E / 256; if (step < 1) step = 1;
        bool ok = true;
        #pragma unroll
        for (int s = 0; s < 8; s++) {
            long long idx = (long long)(threadIdx.x * 8 + s) * step;
            if (idx < E) {
                long long v = p[idx];
                if (v < 0 || v >= (long long)N) ok = false;
            }
        }
        unsigned m = __ballot_sync(0xffffffffu, ok);
        if (threadIdx.x == 0) g_is64 = (m == 0xffffffffu) ? 1 : 0;
    }
}

// ---------------- kernel 2: edge scatter ----------------------------------
__global__ void __launch_bounds__(256)
k_edge(const void* __restrict__ ei, const float* __restrict__ w,
       const float* __restrict__ x, int E, int N) {
    int e = blockIdx.x * blockDim.x + threadIdx.x;
    if (e >= E) return;
    int src, dst;
    if (g_is64) {
        const long long* p = (const long long*)ei;
        src = (int)p[e];
        dst = (int)p[(long long)E + e];
    } else {
        const int* p = (const int*)ei;
        src = p[e];
        dst = p[E + e];
    }
    // safety clamp (protects against a wrong dtype guess faulting)
    src = min(max(src, 0), N - 1);
    dst = min(max(dst, 0), N - 1);

    float we = w[e];
    const float4 xs = *reinterpret_cast<const float4*>(x + 4ll * src);
    float m0 = xs.x * we, m1 = xs.y * we, m2 = xs.z * we, m3 = xs.w * we;

    float* dp = &g_acc[4 * dst];
    asm volatile("red.global.add.v4.f32 [%0], {%1,%2,%3,%4};"
                 :: "l"(dp), "f"(m0), "f"(m1), "f"(m2), "f"(m3)
                 : "memory");
    atomicAdd(&g_cnt[dst], 1.0f);
}

// ---------------- kernel 3: fused node update ------------------------------
__global__ void __launch_bounds__(256)
k_node(const float* __restrict__ x,
       const float* __restrict__ h0, const float* __restrict__ c0,
       const float* __restrict__ convw,
       const float* __restrict__ gwih, const float* __restrict__ gwhh,
       const float* __restrict__ gbih, const float* __restrict__ gbhh,
       const float* __restrict__ lwih, const float* __restrict__ lwhh,
       const float* __restrict__ lbih, const float* __restrict__ lbhh,
       const float* __restrict__ linw, const float* __restrict__ linb,
       float* __restrict__ out, int N) {
    __shared__ float4 s_whh[128 * 8];  // lstm_w_hh [128][32]
    __shared__ float4 s_wih[128];      // lstm_w_ih [128][4]
    __shared__ float  s_lb[128];       // lstm_b_ih + lstm_b_hh
    __shared__ float  s_conv[16];      // conv_weight [4][4]
    __shared__ float4 s_gih[12];       // gru_w_ih [12][4]
    __shared__ float4 s_ghh[12];       // gru_w_hh [12][4]
    __shared__ float  s_gbi[12], s_gbh[12];
    __shared__ float  s_lin[32];
    __shared__ float  s_linb;

    int t = threadIdx.x;
    for (int i = t; i < 1024; i += 256)
        s_whh[i] = reinterpret_cast<const float4*>(lwhh)[i];
    if (t < 128) {
        s_wih[t] = reinterpret_cast<const float4*>(lwih)[t];
        s_lb[t]  = lbih[t] + lbhh[t];
    }
    if (t < 16) s_conv[t] = convw[t];
    if (t < 12) {
        s_gih[t] = reinterpret_cast<const float4*>(gwih)[t];
        s_ghh[t] = reinterpret_cast<const float4*>(gwhh)[t];
        s_gbi[t] = gbih[t];
        s_gbh[t] = gbhh[t];
    }
    if (t < 32) s_lin[t] = linw[t];
    if (t == 0) s_linb = linb[0];
    __syncthreads();

    int n = blockIdx.x * blockDim.x + t;
    if (n >= N) return;

    // mean aggregation, then 4x4 conv matrix
    float inv = frcp(fmaxf(g_cnt[n], 1.0f));
    const float4 sv = *reinterpret_cast<const float4*>(&g_acc[4 * n]);
    float mx[4] = { sv.x * inv, sv.y * inv, sv.z * inv, sv.w * inv };
    float agg[4];
    #pragma unroll
    for (int j = 0; j < 4; j++)
        agg[j] = mx[0] * s_conv[j] + mx[1] * s_conv[4 + j]
               + mx[2] * s_conv[8 + j] + mx[3] * s_conv[12 + j];

    const float4 xv = *reinterpret_cast<const float4*>(x + 4ll * n);
    float xa[4] = { xv.x, xv.y, xv.z, xv.w };

    // GRU cell: h_conv = (1-z)*tanh(i_n + r*h_n) + z*x
    float hc[4];
    #pragma unroll
    for (int c = 0; c < 4; c++) {
        float4 wr = s_gih[c], wz = s_gih[4 + c], wn = s_gih[8 + c];
        float4 ur = s_ghh[c], uz = s_ghh[4 + c], un = s_ghh[8 + c];
        float ir = agg[0]*wr.x + agg[1]*wr.y + agg[2]*wr.z + agg[3]*wr.w + s_gbi[c];
        float iz = agg[0]*wz.x + agg[1]*wz.y + agg[2]*wz.z + agg[3]*wz.w + s_gbi[4 + c];
        float in_= agg[0]*wn.x + agg[1]*wn.y + agg[2]*wn.z + agg[3]*wn.w + s_gbi[8 + c];
        float hr = xa[0]*ur.x + xa[1]*ur.y + xa[2]*ur.z + xa[3]*ur.w + s_gbh[c];
        float hz = xa[0]*uz.x + xa[1]*uz.y + xa[2]*uz.z + xa[3]*uz.w + s_gbh[4 + c];
        float hn = xa[0]*un.x + xa[1]*un.y + xa[2]*un.z + xa[3]*un.w + s_gbh[8 + c];
        float r  = sigf(ir + hr);
        float z  = sigf(iz + hz);
        float nn = tanhf_f(in_ + r * hn);
        hc[c] = (1.0f - z) * nn + z * xa[c];
    }

    // LSTM (seq_len 1): gates = hc @ Wih^T + h_prev @ Whh^T + b
    float4 hp[8];
    const float4* h0v = reinterpret_cast<const float4*>(h0) + 8ll * n;
    #pragma unroll
    for (int k = 0; k < 8; k++) hp[k] = h0v[k];

    const float* cp = c0 + 32ll * n;
    float* hout = out + (long long)N + 32ll * n;
    float* cout = out + (long long)N + 32ll * N + 32ll * n;

    float oacc = 0.0f;
    #pragma unroll 4
    for (int h = 0; h < 32; h++) {
        float ai = s_lb[h], af = s_lb[32 + h], ag = s_lb[64 + h], ao = s_lb[96 + h];
        float4 wi = s_wih[h], wf = s_wih[32 + h], wg = s_wih[64 + h], wo = s_wih[96 + h];
        ai += hc[0]*wi.x + hc[1]*wi.y + hc[2]*wi.z + hc[3]*wi.w;
        af += hc[0]*wf.x + hc[1]*wf.y + hc[2]*wf.z + hc[3]*wf.w;
        ag += hc[0]*wg.x + hc[1]*wg.y + hc[2]*wg.z + hc[3]*wg.w;
        ao += hc[0]*wo.x + hc[1]*wo.y + hc[2]*wo.z + hc[3]*wo.w;
        #pragma unroll
        for (int k = 0; k < 8; k++) {
            float4 u  = hp[k];
            float4 vi = s_whh[(h)      * 8 + k];
            float4 vf = s_whh[(32 + h) * 8 + k];
            float4 vg = s_whh[(64 + h) * 8 + k];
            float4 vo = s_whh[(96 + h) * 8 + k];
            ai += u.x*vi.x + u.y*vi.y + u.z*vi.z + u.w*vi.w;
            af += u.x*vf.x + u.y*vf.y + u.z*vf.z + u.w*vf.w;
            ag += u.x*vg.x + u.y*vg.y + u.z*vg.z + u.w*vg.w;
            ao += u.x*vo.x + u.y*vo.y + u.z*vo.z + u.w*vo.w;
        }
        float ig = sigf(ai), fg = sigf(af), og = sigf(ao), gg = tanhf_f(ag);
        float cn = fg * cp[h] + ig * gg;
        float hn = og * tanhf_f(cn);
        cout[h] = cn;
        hout[h] = hn;
        oacc += fmaxf(hn, 0.0f) * s_lin[h];
    }
    out[n] = oacc + s_linb;
}

// ---------------- launch -----------------------------------------------------
extern "C" void kernel_launch(void* const* d_in, const int* in_sizes, int n_in,
                              void* d_out, int out_size) {
    const float* x    = (const float*)d_in[0];
    const void*  ei   = d_in[1];
    const float* ew   = (const float*)d_in[2];
    const float* h0   = (const float*)d_in[3];
    const float* c0   = (const float*)d_in[4];
    const float* cw   = (const float*)d_in[5];
    const float* gwih = (const float*)d_in[6];
    const float* gwhh = (const float*)d_in[7];
    const float* gbih = (const float*)d_in[8];
    const float* gbhh = (const float*)d_in[9];
    const float* lwih = (const float*)d_in[10];
    const float* lwhh = (const float*)d_in[11];
    const float* lbih = (const float*)d_in[12];
    const float* lbhh = (const float*)d_in[13];
    const float* linw = (const float*)d_in[14];
    const float* linb = (const float*)d_in[15];

    int N = in_sizes[0] / 4;     // x is [N, 4]
    int E = in_sizes[2];         // edge_weight is [E]
    if (N > MAXN) N = MAXN;      // scratch bound (never hit at spec size)

    float* out = (float*)d_out;

    k_init<<<512, 256>>>(ei, E, N);
    k_edge<<<(E + 255) / 256, 256>>>(ei, ew, x, E, N);
    k_node<<<(N + 255) / 256, 256>>>(x, h0, c0, cw, gwih, gwhh, gbih, gbhh,
                                     lwih, lwhh, lbih, lbhh, linw, linb,
                                     out, N);
}

// round 2
// speedup vs baseline: 1.2677x; 1.2677x over previous
#include <cuda_runtime.h>

// ---------------- scratch (static device globals; no allocation) ----------
#define MAXN 200704
// per-node 32B record: {s0,s1,s2,s3, cnt, pad,pad,pad}
__device__ __align__(32) float g_rec[MAXN * 8];
__device__ int g_is64;

typedef unsigned long long u64;

// ---------------- fast math helpers --------------------------------------
__device__ __forceinline__ float fexp(float x) {
    float y;
    asm("ex2.approx.f32 %0, %1;" : "=f"(y) : "f"(x * 1.4426950408889634f));
    return y;
}
__device__ __forceinline__ float frcp(float x) {
    float y;
    asm("rcp.approx.f32 %0, %1;" : "=f"(y) : "f"(x));
    return y;
}
__device__ __forceinline__ float sigf(float x)   { return frcp(1.0f + fexp(-x)); }
__device__ __forceinline__ float tanhf_f(float x){ return 2.0f * sigf(2.0f * x) - 1.0f; }

// packed f32x2 helpers
__device__ __forceinline__ u64 pk2(float a, float b) {
    u64 r; asm("mov.b64 %0, {%1,%2};" : "=l"(r) : "f"(a), "f"(b)); return r;
}
__device__ __forceinline__ void upk2(u64 v, float& a, float& b) {
    asm("mov.b64 {%0,%1}, %2;" : "=f"(a), "=f"(b) : "l"(v));
}
__device__ __forceinline__ u64 fma2(u64 a, u64 b, u64 c) {
    u64 d; asm("fma.rn.f32x2 %0, %1, %2, %3;" : "=l"(d) : "l"(a), "l"(b), "l"(c));
    return d;
}

// ---------------- kernel 1: zero scratch + detect index dtype ------------
__global__ void k_init(const void* __restrict__ ei, int E, int N) {
    int i = blockIdx.x * blockDim.x + threadIdx.x;
    int stride = gridDim.x * blockDim.x;
    float4 z = make_float4(0.f, 0.f, 0.f, 0.f);
    float4* p = (float4*)g_rec;
    int tot = N * 2;  // 2 float4 per node
    for (int j = i; j < tot; j += stride) p[j] = z;

    if (blockIdx.x == 0 && threadIdx.x < 32) {
        const long long* q = (const long long*)ei;
        long long step = E / 256; if (step < 1) step = 1;
        bool ok = true;
        #pragma unroll
        for (int s = 0; s < 8; s++) {
            long long idx = (long long)(threadIdx.x * 8 + s) * step;
            if (idx < E) {
                long long v = q[idx];
                if (v < 0 || v >= (long long)N) ok = false;
            }
        }
        unsigned m = __ballot_sync(0xffffffffu, ok);
        if (threadIdx.x == 0) g_is64 = (m == 0xffffffffu) ? 1 : 0;
    }
}

// ---------------- kernel 2: edge scatter (4 edges / thread) ---------------
__device__ __forceinline__ void scat(int d, float4 g, float we) {
    float* dp = &g_rec[8ll * d];
    asm volatile("red.global.add.v4.f32 [%0], {%1,%2,%3,%4};"
                 :: "l"(dp), "f"(g.x * we), "f"(g.y * we),
                    "f"(g.z * we), "f"(g.w * we) : "memory");
    asm volatile("red.global.add.f32 [%0], %1;"
                 :: "l"(dp + 4), "f"(1.0f) : "memory");
}

__global__ void __launch_bounds__(256)
k_edge(const void* __restrict__ ei, const float* __restrict__ w,
       const float* __restrict__ x, int E) {
    long long base = (long long)(blockIdx.x * 256 + threadIdx.x) * 4;
    if (base >= E) return;
    const float4* __restrict__ xv = (const float4*)x;
    int is64 = g_is64;

    if (base + 4 <= E && (E & 3) == 0) {
        int s0, s1, s2, s3, d0, d1, d2, d3;
        if (is64) {
            const longlong2* p = (const longlong2*)ei;
            long long hs = base >> 1;
            longlong2 a0 = p[hs], a1 = p[hs + 1];
            long long ho = ((long long)E + base) >> 1;
            longlong2 b0 = p[ho], b1 = p[ho + 1];
            s0 = (int)a0.x; s1 = (int)a0.y; s2 = (int)a1.x; s3 = (int)a1.y;
            d0 = (int)b0.x; d1 = (int)b0.y; d2 = (int)b1.x; d3 = (int)b1.y;
        } else {
            const int4* p = (const int4*)ei;
            int4 a = p[base >> 2];
            int4 b = p[((long long)E + base) >> 2];
            s0 = a.x; s1 = a.y; s2 = a.z; s3 = a.w;
            d0 = b.x; d1 = b.y; d2 = b.z; d3 = b.w;
        }
        float4 wq = ((const float4*)w)[base >> 2];
        // issue all gathers first for MLP
        float4 g0 = xv[s0], g1 = xv[s1], g2 = xv[s2], g3 = xv[s3];
        scat(d0, g0, wq.x);
        scat(d1, g1, wq.y);
        scat(d2, g2, wq.z);
        scat(d3, g3, wq.w);
    } else {
        for (int j = 0; j < 4 && base + j < E; j++) {
            long long e = base + j;
            int src, dst;
            if (is64) {
                const long long* p = (const long long*)ei;
                src = (int)p[e];
                dst = (int)p[(long long)E + e];
            } else {
                const int* p = (const int*)ei;
                src = p[e];
                dst = p[E + e];
            }
            scat(dst, xv[src], w[e]);
        }
    }
}

// ---------------- kernel 3: fused node update ------------------------------
__global__ void __launch_bounds__(256)
k_node(const float* __restrict__ x,
       const float* __restrict__ h0, const float* __restrict__ c0,
       const float* __restrict__ convw,
       const float* __restrict__ gwih, const float* __restrict__ gwhh,
       const float* __restrict__ gbih, const float* __restrict__ gbhh,
       const float* __restrict__ lwih, const float* __restrict__ lwhh,
       const float* __restrict__ lbih, const float* __restrict__ lbhh,
       const float* __restrict__ linw, const float* __restrict__ linb,
       float* __restrict__ out, int N) {
    // packed LSTM weights: gate pairs (i,f) and (g,o)
    __shared__ u64 s_if[1024];   // [h][k]: {w_i[h][k], w_f[h][k]}
    __shared__ u64 s_go[1024];   // [h][k]: {w_g[h][k], w_o[h][k]}
    __shared__ u64 s_wif[128];   // [h][c]: wih pairs (i,f)
    __shared__ u64 s_wgo[128];   // [h][c]: wih pairs (g,o)
    __shared__ u64 s_bif[32];    // bias pairs (i,f) (ih+hh combined)
    __shared__ u64 s_bgo[32];
    __shared__ float  s_conv[16];
    __shared__ float4 s_gih[12];
    __shared__ float4 s_ghh[12];
    __shared__ float  s_gbi[12], s_gbh[12];
    __shared__ float  s_lin[32];
    __shared__ float  s_linb;

    int t = threadIdx.x;
    for (int i = t; i < 1024; i += 256) {
        int h = i >> 5, k = i & 31;
        s_if[i] = pk2(lwhh[h * 32 + k],        lwhh[(32 + h) * 32 + k]);
        s_go[i] = pk2(lwhh[(64 + h) * 32 + k], lwhh[(96 + h) * 32 + k]);
    }
    if (t < 128) {
        int h = t >> 2, c = t & 3;
        s_wif[t] = pk2(lwih[h * 4 + c],        lwih[(32 + h) * 4 + c]);
        s_wgo[t] = pk2(lwih[(64 + h) * 4 + c], lwih[(96 + h) * 4 + c]);
    }
    if (t < 32) {
        s_bif[t] = pk2(lbih[t] + lbhh[t],           lbih[32 + t] + lbhh[32 + t]);
        s_bgo[t] = pk2(lbih[64 + t] + lbhh[64 + t], lbih[96 + t] + lbhh[96 + t]);
        s_lin[t] = linw[t];
    }
    if (t < 16) s_conv[t] = convw[t];
    if (t < 12) {
        s_gih[t] = reinterpret_cast<const float4*>(gwih)[t];
        s_ghh[t] = reinterpret_cast<const float4*>(gwhh)[t];
        s_gbi[t] = gbih[t];
        s_gbh[t] = gbhh[t];
    }
    if (t == 0) s_linb = linb[0];
    __syncthreads();

    int n = blockIdx.x * 256 + t;
    if (n >= N) return;

    // ---- mean aggregation + conv 4x4 ----
    const float4* rec4 = (const float4*)g_rec;
    float4 sv = rec4[2 * n];
    float  cv = g_rec[8ll * n + 4];
    float inv = frcp(fmaxf(cv, 1.0f));
    float mx[4] = { sv.x * inv, sv.y * inv, sv.z * inv, sv.w * inv };
    float agg[4];
    #pragma unroll
    for (int j = 0; j < 4; j++)
        agg[j] = mx[0] * s_conv[j] + mx[1] * s_conv[4 + j]
               + mx[2] * s_conv[8 + j] + mx[3] * s_conv[12 + j];

    const float4 xv4 = *reinterpret_cast<const float4*>(x + 4ll * n);
    float xa[4] = { xv4.x, xv4.y, xv4.z, xv4.w };

    // ---- GRU cell ----
    float hc[4];
    #pragma unroll
    for (int c = 0; c < 4; c++) {
        float4 wr = s_gih[c], wz = s_gih[4 + c], wn = s_gih[8 + c];
        float4 ur = s_ghh[c], uz = s_ghh[4 + c], un = s_ghh[8 + c];
        float ir = agg[0]*wr.x + agg[1]*wr.y + agg[2]*wr.z + agg[3]*wr.w + s_gbi[c];
        float iz = agg[0]*wz.x + agg[1]*wz.y + agg[2]*wz.z + agg[3]*wz.w + s_gbi[4 + c];
        float in_= agg[0]*wn.x + agg[1]*wn.y + agg[2]*wn.z + agg[3]*wn.w + s_gbi[8 + c];
        float hr = xa[0]*ur.x + xa[1]*ur.y + xa[2]*ur.z + xa[3]*ur.w + s_gbh[c];
        float hz = xa[0]*uz.x + xa[1]*uz.y + xa[2]*uz.z + xa[3]*uz.w + s_gbh[4 + c];
        float hn = xa[0]*un.x + xa[1]*un.y + xa[2]*un.z + xa[3]*un.w + s_gbh[8 + c];
        float r  = sigf(ir + hr);
        float z  = sigf(iz + hz);
        float nn = tanhf_f(in_ + r * hn);
        hc[c] = (1.0f - z) * nn + z * xa[c];
    }

    // ---- LSTM (seq 1), packed f32x2 gate math ----
    u64 upp[32];  // h_prev duplicated pairs
    const float4* h0v = reinterpret_cast<const float4*>(h0) + 8ll * n;
    #pragma unroll
    for (int k = 0; k < 8; k++) {
        float4 u = h0v[k];
        upp[4*k + 0] = pk2(u.x, u.x);
        upp[4*k + 1] = pk2(u.y, u.y);
        upp[4*k + 2] = pk2(u.z, u.z);
        upp[4*k + 3] = pk2(u.w, u.w);
    }
    u64 hcp[4];
    #pragma unroll
    for (int c = 0; c < 4; c++) hcp[c] = pk2(hc[c], hc[c]);

    const float4* cp4 = reinterpret_cast<const float4*>(c0 + 32ll * n);
    float4* hout = reinterpret_cast<float4*>(out + (long long)N + 32ll * n);
    float4* cout = reinterpret_cast<float4*>(out + (long long)N + 32ll * N + 32ll * n);

    float oacc = 0.0f;
    #pragma unroll 1
    for (int hq = 0; hq < 8; hq++) {
        float4 cprev4 = cp4[hq];
        float cpv[4] = { cprev4.x, cprev4.y, cprev4.z, cprev4.w };
        float hb[4], cb[4];
        #pragma unroll
        for (int j = 0; j < 4; j++) {
            int h = hq * 4 + j;
            u64 aif = s_bif[h];
            u64 ago = s_bgo[h];
            #pragma unroll
            for (int c = 0; c < 4; c++) {
                aif = fma2(hcp[c], s_wif[h * 4 + c], aif);
                ago = fma2(hcp[c], s_wgo[h * 4 + c], ago);
            }
            const ulonglong2* pif = (const ulonglong2*)&s_if[h * 32];
            const ulonglong2* pgo = (const ulonglong2*)&s_go[h * 32];
            #pragma unroll
            for (int q = 0; q < 16; q++) {
                ulonglong2 vif = pif[q];
                ulonglong2 vgo = pgo[q];
                aif = fma2(upp[2*q],     vif.x, aif);
                aif = fma2(upp[2*q + 1], vif.y, aif);
                ago = fma2(upp[2*q],     vgo.x, ago);
                ago = fma2(upp[2*q + 1], vgo.y, ago);
            }
            float ai, af, ag, ao;
            upk2(aif, ai, af);
            upk2(ago, ag, ao);
            float ig = sigf(ai), fg = sigf(af), og = sigf(ao), gg = tanhf_f(ag);
            float cn = fg * cpv[j] + ig * gg;
            float hn = og * tanhf_f(cn);
            cb[j] = cn; hb[j] = hn;
            oacc += fmaxf(hn, 0.0f) * s_lin[h];
        }
        cout[hq] = make_float4(cb[0], cb[1], cb[2], cb[3]);
        hout[hq] = make_float4(hb[0], hb[1], hb[2], hb[3]);
    }
    out[n] = oacc + s_linb;
}

// ---------------- launch -----------------------------------------------------
extern "C" void kernel_launch(void* const* d_in, const int* in_sizes, int n_in,
                              void* d_out, int out_size) {
    const float* x    = (const float*)d_in[0];
    const void*  ei   = d_in[1];
    const float* ew   = (const float*)d_in[2];
    const float* h0   = (const float*)d_in[3];
    const float* c0   = (const float*)d_in[4];
    const float* cw   = (const float*)d_in[5];
    const float* gwih = (const float*)d_in[6];
    const float* gwhh = (const float*)d_in[7];
    const float* gbih = (const float*)d_in[8];
    const float* gbhh = (const float*)d_in[9];
    const float* lwih = (const float*)d_in[10];
    const float* lwhh = (const float*)d_in[11];
    const float* lbih = (const float*)d_in[12];
    const float* lbhh = (const float*)d_in[13];
    const float* linw = (const float*)d_in[14];
    const float* linb = (const float*)d_in[15];

    int N = in_sizes[0] / 4;
    int E = in_sizes[2];
    if (N > MAXN) N = MAXN;

    float* out = (float*)d_out;

    k_init<<<1024, 256>>>(ei, E, N);
    long long nth = ((long long)E + 3) / 4;
    int eblocks = (int)((nth + 255) / 256);
    k_edge<<<eblocks, 256>>>(ei, ew, x, E);
    k_node<<<(N + 255) / 256, 256>>>(x, h0, c0, cw, gwih, gwhh, gbih, gbhh,
                                     lwih, lwhh, lbih, lbhh, linw, linb,
                                     out, N);
}